// round 11
// baseline (speedup 1.0000x reference)
#include <cuda_runtime.h>
#include <math.h>
#include <stdint.h>

#define H 96
#define W 96
#define C 128
#define OCH 128
#define BATCH 2
#define HP 98
#define WP 98
#define HWIMG (H*W)              // 9216
#define NPIX (BATCH*H*W)         // 18432
#define PT 128                   // pixels per block
#define NBLK (NPIX/PT)           // 144

#define XS 272                   // smem row stride (256B data + 16B pad)
#define TS (128*XS)              // one 128x128 bf16 tile = 34816B

// dynamic smem: [Whi][Wlo][X0hi][X0lo][X1hi][X1lo]
#define SM_WHI 0
#define SM_X0  (2*TS)
#define SMEM_BYTES (6*TS)        // 208896

// ---------------- scratch (device globals; no allocation allowed) ----------
__device__ float    g_xp[BATCH*HP*WP*C];   // padded NHWC input (~9.8MB, borders 0)
__device__ uint32_t g_wbf2[9*2*128*64];    // [n][hi/lo][o][kpair] bf16x2 weights
__device__ float    g_wmeta[9*21*C];       // meta conv weights [n][f][c]
__device__ float4   g_mg[NPIX*9];          // bilinear weights (lt, rb, lb, rt)
__device__ int4     g_midx[NPIX*9];        // flat gather indices into xp (pixel units)

// ---------------- helpers ----------------------------------------------------
static __device__ __forceinline__ uint32_t smem_u32(const void* p) {
    uint32_t a;
    asm("{ .reg .u64 t; cvta.to.shared.u64 t, %1; cvt.u32.u64 %0, t; }" : "=r"(a) : "l"(p));
    return a;
}
static __device__ __forceinline__ void cp16(uint32_t dst_smem, const void* src) {
    asm volatile("cp.async.cg.shared.global [%0], [%1], 16;" :: "r"(dst_smem), "l"(src));
}
#define CP_COMMIT() asm volatile("cp.async.commit_group;")
#define CP_WAIT0()  asm volatile("cp.async.wait_group 0;")

static __device__ __forceinline__ uint32_t pack_bf16x2(float hi, float lo) {
    uint32_t r;
    asm("cvt.rn.bf16x2.f32 %0, %1, %2;" : "=r"(r) : "f"(hi), "f"(lo));
    return r;
}
static __device__ __forceinline__ float bf16hi_f(uint32_t p) { return __uint_as_float(p & 0xffff0000u); }
static __device__ __forceinline__ float bf16lo_f(uint32_t p) { return __uint_as_float(p << 16); }

static __device__ __forceinline__ void ldsm4(uint32_t a, uint32_t& r0, uint32_t& r1,
                                             uint32_t& r2, uint32_t& r3) {
    asm volatile("ldmatrix.sync.aligned.m8n8.x4.shared.b16 {%0,%1,%2,%3}, [%4];"
                 : "=r"(r0), "=r"(r1), "=r"(r2), "=r"(r3) : "r"(a));
}
static __device__ __forceinline__ void mma16816(float* d, const uint32_t* a,
                                                const uint32_t* b) {
    asm volatile("mma.sync.aligned.m16n8k16.row.col.f32.bf16.bf16.f32 "
                 "{%0,%1,%2,%3}, {%4,%5,%6,%7}, {%8,%9}, {%0,%1,%2,%3};"
                 : "+f"(d[0]), "+f"(d[1]), "+f"(d[2]), "+f"(d[3])
                 : "r"(a[0]), "r"(a[1]), "r"(a[2]), "r"(a[3]), "r"(b[0]), "r"(b[1]));
}

// blend 4 taps with bilinear weights, split bf16 hi/lo, store 8B to X row
static __device__ __forceinline__ void blend_sts(float4 t0, float4 t1, float4 t2, float4 t3,
                                                 float4 g, char* xrow, int lane) {
    float4 v;
    v.x = g.x*t0.x + g.y*t1.x + g.z*t2.x + g.w*t3.x;
    v.y = g.x*t0.y + g.y*t1.y + g.z*t2.y + g.w*t3.y;
    v.z = g.x*t0.z + g.y*t1.z + g.z*t2.z + g.w*t3.z;
    v.w = g.x*t0.w + g.y*t1.w + g.z*t2.w + g.w*t3.w;
    uint32_t p01 = pack_bf16x2(v.y, v.x);
    uint32_t p23 = pack_bf16x2(v.w, v.z);
    uint32_t q01 = pack_bf16x2(v.y - bf16hi_f(p01), v.x - bf16lo_f(p01));
    uint32_t q23 = pack_bf16x2(v.w - bf16hi_f(p23), v.z - bf16lo_f(p23));
    *(uint2*)(xrow + 8*lane)      = make_uint2(p01, p23);
    *(uint2*)(xrow + TS + 8*lane) = make_uint2(q01, q23);
}

// ---------------- weight prep ----------------------------------------------
__global__ void prep_weights(const float* __restrict__ conv_w,
                             const float* __restrict__ pconv_w,
                             const float* __restrict__ adconv_w) {
    int lin = blockIdx.x * blockDim.x + threadIdx.x;
    if (lin < 9*128*64) {                     // (n, o, kpair)
        int kp = lin & 63;
        int o  = (lin >> 6) & 127;
        int n  = lin >> 13;
        float w0 = conv_w[(o*C + 2*kp)*9 + n];
        float w1 = conv_w[(o*C + 2*kp + 1)*9 + n];
        uint32_t phi = pack_bf16x2(w1, w0);   // lo16 = even channel
        float l0 = w0 - bf16lo_f(phi);
        float l1 = w1 - bf16hi_f(phi);
        uint32_t plo = pack_bf16x2(l1, l0);
        g_wbf2[(((size_t)n*2 + 0)*128 + o)*64 + kp] = phi;
        g_wbf2[(((size_t)n*2 + 1)*128 + o)*64 + kp] = plo;
    }
    if (lin < 9*21*C) {
        int c = lin % C;
        int f = (lin / C) % 21;
        int n = lin / (21*C);
        g_wmeta[lin] = (f < 18) ? pconv_w[(f*C + c)*9 + n]
                                : adconv_w[((f-18)*C + c)*9 + n];
    }
}

// ---------------- NCHW -> padded NHWC transpose -----------------------------
__global__ void transpose_pad(const float* __restrict__ x) {
    __shared__ float tile[32][33];
    int b = blockIdx.z, i = blockIdx.y;
    int tj = blockIdx.x % 3;
    int tc = blockIdx.x / 3;
    int j0 = tj * 32, c0 = tc * 32;
    int tx = threadIdx.x, ty = threadIdx.y;   // 32 x 8

    const float* src = x + ((size_t)(b*C) * H + i) * W;
    #pragma unroll
    for (int q = 0; q < 4; q++) {
        int c = c0 + ty + q*8;
        tile[ty + q*8][tx] = src[(size_t)c * H * W + j0 + tx];
    }
    __syncthreads();
    float* dst = g_xp + (((size_t)b*HP) + (i+1)) * WP * C;
    #pragma unroll
    for (int q = 0; q < 4; q++) {
        int jj = j0 + ty + q*8;
        dst[(size_t)(jj+1)*C + c0 + tx] = tile[tx][ty + q*8];
    }
}

// ---------------- meta: 4 pixels per warp, smem reduction --------------------
__global__ void __launch_bounds__(256) meta_kernel(const float* __restrict__ pconv_b,
                                                   const float* __restrict__ adconv_b) {
    __shared__ float red[8][4][24];
    int gwarp = (blockIdx.x * blockDim.x + threadIdx.x) >> 5;
    int wib   = (threadIdx.x >> 5);
    int lane  = threadIdx.x & 31;
    if (gwarp >= NPIX/4) return;
    int pix0 = gwarp * 4;
    int b = pix0 / (H*W);
    int rem = pix0 % (H*W);
    int i = rem / W;
    int j0 = rem % W;          // multiple of 4, so all 4 px share row i

    float part[4][21];
    #pragma unroll
    for (int p = 0; p < 4; p++)
        #pragma unroll
        for (int f = 0; f < 21; f++) part[p][f] = 0.f;

    const float4* wm4 = (const float4*)g_wmeta;
    #pragma unroll
    for (int n = 0; n < 9; n++) {
        int kr = n / 3, kc = n % 3;
        float4 xv[4];
        #pragma unroll
        for (int p = 0; p < 4; p++)
            xv[p] = ((const float4*)(g_xp + (size_t)(((b*HP) + (i+kr))*WP + (j0+p+kc)) * C))[lane];
        const float4* wrow = wm4 + (size_t)(n*21)*32 + lane;
        #pragma unroll
        for (int f = 0; f < 21; f++) {
            float4 wv = wrow[(size_t)f*32];
            #pragma unroll
            for (int p = 0; p < 4; p++)
                part[p][f] += xv[p].x*wv.x + xv[p].y*wv.y + xv[p].z*wv.z + xv[p].w*wv.w;
        }
    }
    #pragma unroll
    for (int p = 0; p < 4; p++)
        #pragma unroll
        for (int f = 0; f < 21; f++) {
            float s = part[p][f];
            #pragma unroll
            for (int sh = 16; sh; sh >>= 1)
                s += __shfl_xor_sync(0xffffffffu, s, sh);
            if (lane == 0) red[wib][p][f] = s;
        }
    __syncwarp();

    #pragma unroll
    for (int p = 0; p < 4; p++) {
        if (lane < 9) {
            int n = lane;
            int j = j0 + p;
            int pix = pix0 + p;
            float offx = red[wib][p][n]     + pconv_b[n];
            float offy = red[wib][p][9 + n] + pconv_b[9 + n];
            int m = n % 3;
            float adv = red[wib][p][18 + m] + adconv_b[m];
            float adb = 1.f - 1.f / (1.f + expf(-adv));   // 1 - sigmoid
            float pnx = (float)(n / 3 - 1);
            float pny = (float)(n % 3 - 1);
            float px = (float)(i + 1) + pnx * (1.f + 2.f*adb) + offx;
            float py = (float)(j + 1) + pny * (1.f + 2.f*adb) + offy;

            float flx = floorf(px), fly = floorf(py);
            int qltx = min(max((int)flx,     0), HP-1);
            int qlty = min(max((int)fly,     0), WP-1);
            int qrbx = min(max((int)flx + 1, 0), HP-1);
            int qrby = min(max((int)fly + 1, 0), WP-1);
            bool mx = (px < 1.f) || (px > (float)(HP-2));
            bool my = (py < 1.f) || (py > (float)(WP-2));
            float pxe = mx ? fminf(fmaxf(flx, 0.f), (float)(HP-1)) : fminf(fmaxf(px, 0.f), (float)(HP-1));
            float pye = my ? fminf(fmaxf(fly, 0.f), (float)(WP-1)) : fminf(fmaxf(py, 0.f), (float)(WP-1));

            float glt_x = 1.f + ((float)qltx - pxe);
            float glt_y = 1.f + ((float)qlty - pye);
            float grb_x = 1.f - ((float)qrbx - pxe);
            float grb_y = 1.f - ((float)qrby - pye);

            float4 g = make_float4(glt_x*glt_y, grb_x*grb_y, glt_x*grb_y, grb_x*glt_y);
            int base = b * HP * WP;
            int4 idx = make_int4(base + qltx*WP + qlty,
                                 base + qrbx*WP + qrby,
                                 base + qltx*WP + qrby,
                                 base + qrbx*WP + qlty);
            g_mg[(size_t)pix*9 + n]   = g;
            g_midx[(size_t)pix*9 + n] = idx;
        }
    }
}

// ---------------- main: pipelined mma.sync bf16-split gather-GEMM -----------
// D[128 o][128 px] = sum over 9 n: Whi*Xhi + Whi*Xlo + Wlo*Xhi (fp32 accum)
// 16 warps, warp tile 32 o x 32 px; gather for n+1 interleaved with MMA of n
__global__ void __launch_bounds__(512, 1) main_kernel(float* __restrict__ out) {
    extern __shared__ char S[];
    uint32_t sb = smem_u32(S);
    int tid  = threadIdx.x;
    int wid  = tid >> 5;
    int lane = tid & 31;
    int pt0  = blockIdx.x * PT;

    int o0  = (wid >> 2) * 32;
    int px0 = (wid & 3) * 32;

    int arow = (lane & 7) + ((lane >> 3) & 1) * 8;
    int akad = (lane >> 4) * 8;
    int brow = (lane & 7) + (lane >> 4) * 8;
    int bkad = ((lane >> 3) & 1) * 8;

    uint32_t aoff = sb + SM_WHI + (uint32_t)(o0 + arow)*XS + (uint32_t)akad*2;
    uint32_t boff_base = sb + (uint32_t)(px0 + brow)*XS + (uint32_t)bkad*2;

    float d[8][4];
    #pragma unroll
    for (int t = 0; t < 8; t++)
        #pragma unroll
        for (int q = 0; q < 4; q++) d[t][q] = 0.f;

    const float4* xp4 = (const float4*)g_xp;

    // ---- prologue: stage W(0); gather X(0) into buf0 ----
    {
        int th = tid >> 8;                 // 0 = hi, 1 = lo
        int r  = (tid >> 1) & 127;         // o row
        int hh = tid & 1;                  // half-row (128B)
        const char* src = (const char*)g_wbf2 + (((size_t)0*2 + th)*128 + r)*256 + hh*128;
        uint32_t dst = sb + SM_WHI + th*TS + (uint32_t)r*XS + hh*128;
        #pragma unroll
        for (int t = 0; t < 8; t++) cp16(dst + t*16, src + t*16);
        CP_COMMIT();
    }
    #pragma unroll 1
    for (int p = 0; p < 8; p++) {
        int px = wid*8 + p;
        size_t m = (size_t)(pt0 + px)*9 + 0;
        int4 id = g_midx[m];
        float4 g = g_mg[m];
        float4 t0 = xp4[(size_t)id.x*32 + lane];
        float4 t1 = xp4[(size_t)id.y*32 + lane];
        float4 t2 = xp4[(size_t)id.z*32 + lane];
        float4 t3 = xp4[(size_t)id.w*32 + lane];
        blend_sts(t0, t1, t2, t3, g, S + SM_X0 + (size_t)px*XS, lane);
    }

    // ---- main loop over 9 taps ----
    for (int n = 0; n < 9; n++) {
        CP_WAIT0();        // W(n) landed (own group)
        __syncthreads();   // W(n) + X(n) visible block-wide
        uint32_t xcons = SM_X0 + (uint32_t)(n & 1) * (2*TS);
        uint32_t xprod = SM_X0 + (uint32_t)((n + 1) & 1) * (2*TS);
        uint32_t boff  = boff_base + xcons;
        bool pf = (n < 8);

        int4 ida, nida;
        float4 ga, nga;
        if (pf) {
            size_t m = (size_t)(pt0 + wid*8)*9 + (n + 1);
            ida = g_midx[m];
            ga  = g_mg[m];
        }

        #pragma unroll 1
        for (int s = 0; s < 8; s++) {
            // prefetch taps for pixel (wid*8 + s) of n+1
            float4 T0, T1, T2, T3;
            if (pf) {
                T0 = xp4[(size_t)ida.x*32 + lane];
                T1 = xp4[(size_t)ida.y*32 + lane];
                T2 = xp4[(size_t)ida.z*32 + lane];
                T3 = xp4[(size_t)ida.w*32 + lane];
                if (s < 7) {    // rotate meta for next pixel
                    size_t m = (size_t)(pt0 + wid*8 + s + 1)*9 + (n + 1);
                    nida = g_midx[m];
                    nga  = g_mg[m];
                }
            }

            // MMA step s (K slice 16)
            uint32_t ks = (uint32_t)s * 32;
            uint32_t bh[8], bl[8];
            ldsm4(boff + ks,              bh[0], bh[1], bh[2], bh[3]);
            ldsm4(boff + ks + 16*XS,      bh[4], bh[5], bh[6], bh[7]);
            ldsm4(boff + ks + TS,         bl[0], bl[1], bl[2], bl[3]);
            ldsm4(boff + ks + TS + 16*XS, bl[4], bl[5], bl[6], bl[7]);
            #pragma unroll
            for (int mt = 0; mt < 2; mt++) {
                uint32_t a[4];
                uint32_t ab = aoff + ks + (uint32_t)mt*16*XS;
                ldsm4(ab, a[0], a[1], a[2], a[3]);
                #pragma unroll
                for (int nt = 0; nt < 4; nt++) {
                    mma16816(d[mt*4 + nt], a, bh + nt*2);
                    mma16816(d[mt*4 + nt], a, bl + nt*2);
                }
                ldsm4(ab + TS, a[0], a[1], a[2], a[3]);   // W lo
                #pragma unroll
                for (int nt = 0; nt < 4; nt++)
                    mma16816(d[mt*4 + nt], a, bh + nt*2);
            }

            // blend + store pixel into produce buffer
            if (pf) {
                char* xr = S + xprod + (size_t)(wid*8 + s)*XS;
                blend_sts(T0, T1, T2, T3, ga, xr, lane);
                ida = nida; ga = nga;
            }
        }

        __syncthreads();   // MMA(n) done with W before restage; STS(n+1) done
        if (pf) {          // stage W(n+1)
            int th = tid >> 8;
            int r  = (tid >> 1) & 127;
            int hh = tid & 1;
            const char* src = (const char*)g_wbf2 + (((size_t)(n+1)*2 + th)*128 + r)*256 + hh*128;
            uint32_t dst = sb + SM_WHI + th*TS + (uint32_t)r*XS + hh*128;
            #pragma unroll
            for (int t = 0; t < 8; t++) cp16(dst + t*16, src + t*16);
            CP_COMMIT();
        }
    }

    // ---- epilogue: write NCHW output from fragments ----
    int b   = pt0 / HWIMG;
    int pim = pt0 % HWIMG;
    float* base = out + (size_t)b*OCH*HWIMG + pim;
    int g4 = lane >> 2, t4 = lane & 3;
    #pragma unroll
    for (int mt = 0; mt < 2; mt++) {
        #pragma unroll
        for (int nt = 0; nt < 4; nt++) {
            int o   = o0 + mt*16 + g4;
            int pxl = px0 + nt*8 + 2*t4;
            float* p0 = base + (size_t)o*HWIMG + pxl;
            *(float2*)p0 = make_float2(d[mt*4+nt][0], d[mt*4+nt][1]);
            *(float2*)(p0 + (size_t)8*HWIMG) = make_float2(d[mt*4+nt][2], d[mt*4+nt][3]);
        }
    }
}

// ---------------- launcher ---------------------------------------------------
extern "C" void kernel_launch(void* const* d_in, const int* in_sizes, int n_in,
                              void* d_out, int out_size) {
    const float* x        = (const float*)d_in[0];
    const float* conv_w   = (const float*)d_in[1];
    const float* pconv_w  = (const float*)d_in[2];
    const float* pconv_b  = (const float*)d_in[3];
    const float* adconv_w = (const float*)d_in[4];
    const float* adconv_b = (const float*)d_in[5];
    float* out = (float*)d_out;

    cudaFuncSetAttribute(main_kernel, cudaFuncAttributeMaxDynamicSharedMemorySize, SMEM_BYTES);

    prep_weights<<<288, 256>>>(conv_w, pconv_w, adconv_w);
    transpose_pad<<<dim3(12, 96, 2), dim3(32, 8)>>>(x);
    meta_kernel<<<(NPIX/4)/8, 256>>>(pconv_b, adconv_b);
    main_kernel<<<NBLK, 512, SMEM_BYTES>>>(out);
}